// round 10
// baseline (speedup 1.0000x reference)
#include <cuda_runtime.h>
#include <cuda_bf16.h>
#include <math.h>

// Problem constants
#define Bq      4
#define C       192
#define C3      576
#define HEADS   8
#define HD      24
#define HIDDEN  510
#define FF2     1020
#define Hh      128
#define Wd      128
#define HW      16384
#define EPS_LN  1e-5f
#define KOUTP   512

// ---------------------------------------------------------------------------
// Static scratch
// ---------------------------------------------------------------------------
__device__ float g_t2  [(size_t)Bq * 2 * C * HW];  // q,k post-dw (fp32)
__device__ float g_xmid[(size_t)Bq * C * HW];
__device__ float g_attn[Bq * HEADS * HD * HD];
__device__ float g_sq  [Bq * 2 * C];
__device__ float g_invq[Bq * C];
__device__ float g_invk[Bq * C];

__device__ __nv_bfloat16 g_t1b [(size_t)Bq * FF2    * HW];  // pre-dw (bf16)
__device__ __nv_bfloat16 g_vb  [(size_t)Bq * C      * HW];  // v post-dw (bf16)
__device__ __nv_bfloat16 g_lnb [(size_t)Bq * C      * HW];  // LN output (bf16)
__device__ __nv_bfloat16 g_gate[(size_t)Bq * HIDDEN * HW];  // gated FFN (bf16)
__device__ __nv_bfloat16 g_wqkvb[C3 * C];
__device__ __nv_bfloat16 g_winb [FF2 * C];
__device__ __nv_bfloat16 g_woutb[C * KOUTP];
__device__ __nv_bfloat16 g_wmb  [Bq * C * C];

// ---------------------------------------------------------------------------
// Weight fp32 -> bf16 conversion (with K padding)
// ---------------------------------------------------------------------------
__global__ void convw_kernel(const float* __restrict__ src, __nv_bfloat16* __restrict__ dst,
                             int M, int K, int Kpad)
{
    int idx = blockIdx.x * 256 + threadIdx.x;
    if (idx >= M * Kpad) return;
    int m = idx / Kpad, k = idx % Kpad;
    dst[idx] = (k < K) ? __float2bfloat16(src[(size_t)m * K + k]) : __float2bfloat16(0.f);
}

// ---------------------------------------------------------------------------
// Single-read LayerNorm over channel dim -> bf16
// ---------------------------------------------------------------------------
__global__ void __launch_bounds__(256)
ln_kernel(const float* __restrict__ x, const float* __restrict__ w,
          const float* __restrict__ bias, __nv_bfloat16* __restrict__ out)
{
    int blk = blockIdx.x;
    int b   = blk >> 8;
    int p0  = (blk & 255) << 6;
    int px  = threadIdx.x & 63;
    int cg  = threadIdx.x >> 6;

    const float* xp = x + (size_t)b * C * HW + p0 + px;
    float v[48];
    float s = 0.f, s2 = 0.f;
    #pragma unroll
    for (int c = 0; c < 48; c++) {
        float t = xp[(size_t)(cg * 48 + c) * HW];
        v[c] = t; s += t; s2 += t * t;
    }

    __shared__ float ss[4][64], ss2[4][64];
    ss[cg][px] = s; ss2[cg][px] = s2;
    __syncthreads();
    float S  = ss[0][px]  + ss[1][px]  + ss[2][px]  + ss[3][px];
    float S2 = ss2[0][px] + ss2[1][px] + ss2[2][px] + ss2[3][px];
    float mu  = S * (1.f / C);
    float var = S2 * (1.f / C) - mu * mu;
    float r   = rsqrtf(var + EPS_LN);

    __nv_bfloat16* op = out + (size_t)b * C * HW + p0 + px;
    #pragma unroll
    for (int c = 0; c < 48; c++) {
        int ch = cg * 48 + c;
        op[(size_t)ch * HW] = __float2bfloat16((v[c] - mu) * r * __ldg(&w[ch]) + __ldg(&bias[ch]));
    }
}

// ---------------------------------------------------------------------------
// BF16 GEMM, 2-stage cp.async pipeline + ldmatrix fragments
// C[b] (M x 16384) = W[b] (M x K bf16) @ X[b] (Kreal x 16384 bf16) (+ Res)
// BM=128 BN=128 BK=16; 8 warps; warp tile 32m x 64n; K compile-time
// ---------------------------------------------------------------------------
#define BM 128
#define BN 128
#define BK 16
#define APITCH 24
#define GN 16384

__device__ __forceinline__ unsigned pack_bf2(float lo, float hi)
{
    __nv_bfloat162 v = __floats2bfloat162_rn(lo, hi);
    return *(unsigned*)&v;
}

__device__ __forceinline__ void mma_bf16(float c[4], const unsigned a[4], const unsigned* b2)
{
    asm volatile(
        "mma.sync.aligned.m16n8k16.row.col.f32.bf16.bf16.f32 "
        "{%0,%1,%2,%3}, {%4,%5,%6,%7}, {%8,%9}, {%0,%1,%2,%3};"
        : "+f"(c[0]), "+f"(c[1]), "+f"(c[2]), "+f"(c[3])
        : "r"(a[0]), "r"(a[1]), "r"(a[2]), "r"(a[3]), "r"(b2[0]), "r"(b2[1]));
}

__device__ __forceinline__ void ldsm_x4(unsigned r[4], unsigned addr)
{
    asm volatile("ldmatrix.sync.aligned.m8n8.x4.shared.b16 {%0,%1,%2,%3}, [%4];"
                 : "=r"(r[0]), "=r"(r[1]), "=r"(r[2]), "=r"(r[3]) : "r"(addr));
}

__device__ __forceinline__ void ldsm_x4_t(unsigned r[4], unsigned addr)
{
    asm volatile("ldmatrix.sync.aligned.m8n8.x4.trans.shared.b16 {%0,%1,%2,%3}, [%4];"
                 : "=r"(r[0]), "=r"(r[1]), "=r"(r[2]), "=r"(r[3]) : "r"(addr));
}

__device__ __forceinline__ void cp16(unsigned dst, const void* src, int bytes)
{
    asm volatile("cp.async.cg.shared.global [%0], [%1], 16, %2;"
                 :: "r"(dst), "l"(src), "r"(bytes));
}

template<int K, bool OUTBF16>
__global__ void __launch_bounds__(256, 2)
bf16_gemm_kernel(const __nv_bfloat16* __restrict__ Wt, const __nv_bfloat16* __restrict__ X,
                 void* __restrict__ Om, const float* __restrict__ Res,
                 int M, int Kreal, long wB, long xB, long cB)
{
    constexpr int NIT = K / BK;
    const int b = blockIdx.z;
    const __nv_bfloat16* Wb = Wt + (size_t)b * wB;
    const __nv_bfloat16* Xb = X  + (size_t)b * xB;
    const float* Rb = Res ? (Res + (size_t)b * cB) : nullptr;

    __shared__ __nv_bfloat16 As[2][BM][APITCH];
    __shared__ __nv_bfloat16 Bs[2][BK][BN];

    const int tid  = threadIdx.x;
    const int lane = tid & 31, warp = tid >> 5;
    const int wm = warp & 3;
    const int wn = warp >> 2;
    const int g  = lane >> 2;
    const int tg = lane & 3;

    const int m0 = blockIdx.y * BM;
    const int n0 = blockIdx.x * BN;

    float acc[2][8][4];
    #pragma unroll
    for (int i = 0; i < 2; i++)
        #pragma unroll
        for (int j = 0; j < 8; j++)
            #pragma unroll
            for (int q = 0; q < 4; q++) acc[i][j][q] = 0.f;

    // loop-invariant ldmatrix addresses (per stage buffer)
    unsigned aaddr[2][2], baddr[2][4];
    {
        int arow = wm * 32 + (lane & 15);
        int koff = (lane >> 4) * 8;
        int kk = lane & 15;
        #pragma unroll
        for (int bf = 0; bf < 2; bf++) {
            #pragma unroll
            for (int i = 0; i < 2; i++)
                aaddr[bf][i] = (unsigned)__cvta_generic_to_shared(&As[bf][arow + i * 16][koff]);
            #pragma unroll
            for (int jp = 0; jp < 4; jp++) {
                int cidx = wn * 8 + jp * 2 + (lane >> 4);
                int col  = (cidx ^ (kk & 7)) * 8;
                baddr[bf][jp] = (unsigned)__cvta_generic_to_shared(&Bs[bf][kk][col]);
            }
        }
    }

    // global load indices
    const int ar  = tid >> 1;
    const int ah  = (tid & 1) * 8;
    const int kq  = tid >> 4;
    const int cq  = tid & 15;
    const int bcol = (cq ^ (kq & 7)) * 8;

    const int abytes = (m0 + ar < M) ? 16 : 0;
    unsigned adst[2], bdst[2];
    #pragma unroll
    for (int bf = 0; bf < 2; bf++) {
        adst[bf] = (unsigned)__cvta_generic_to_shared(&As[bf][ar][ah]);
        bdst[bf] = (unsigned)__cvta_generic_to_shared(&Bs[bf][kq][bcol]);
    }

    // prologue: stage 0
    {
        cp16(adst[0], Wb + (size_t)(m0 + ar) * K + ah, abytes);
        int kr = kq;
        cp16(bdst[0], Xb + (size_t)kr * GN + n0 + cq * 8, (kr < Kreal) ? 16 : 0);
        asm volatile("cp.async.commit_group;");
    }

    #pragma unroll
    for (int it = 0; it < NIT; it++) {
        const int bf = it & 1;
        asm volatile("cp.async.wait_group 0;");
        __syncthreads();

        if (it + 1 < NIT) {
            int kt = (it + 1) * BK;
            cp16(adst[bf ^ 1], Wb + (size_t)(m0 + ar) * K + kt + ah, abytes);
            int kr = kt + kq;
            cp16(bdst[bf ^ 1], Xb + (size_t)kr * GN + n0 + cq * 8, (kr < Kreal) ? 16 : 0);
            asm volatile("cp.async.commit_group;");
        }

        unsigned af[2][4], bq4[4][4];
        ldsm_x4(af[0], aaddr[bf][0]);
        ldsm_x4(af[1], aaddr[bf][1]);
        #pragma unroll
        for (int jp = 0; jp < 4; jp++) ldsm_x4_t(bq4[jp], baddr[bf][jp]);
        #pragma unroll
        for (int i = 0; i < 2; i++)
            #pragma unroll
            for (int j = 0; j < 8; j++)
                mma_bf16(acc[i][j], af[i], &bq4[j >> 1][(j & 1) * 2]);
    }

    // Epilogue
    #pragma unroll
    for (int i = 0; i < 2; i++) {
        int r0 = m0 + wm * 32 + i * 16 + g;
        #pragma unroll
        for (int j = 0; j < 8; j++) {
            int cc = n0 + wn * 64 + j * 8 + tg * 2;
            #pragma unroll
            for (int h = 0; h < 2; h++) {
                int rr = r0 + h * 8;
                if (rr >= M) continue;
                size_t o = (size_t)rr * GN + cc;
                float vx = acc[i][j][h * 2], vy = acc[i][j][h * 2 + 1];
                if (Rb) { float2 r = *(const float2*)&Rb[o]; vx += r.x; vy += r.y; }
                if (OUTBF16) {
                    *(unsigned*)&((__nv_bfloat16*)Om)[(size_t)b * cB + o] = pack_bf2(vx, vy);
                } else {
                    *(float2*)&((float*)Om)[(size_t)b * cB + o] = make_float2(vx, vy);
                }
            }
        }
    }
}

// ---------------------------------------------------------------------------
// Tiled depthwise 3x3 (bf16 input), strip = 32 rows; smem halo 34x128 fp32
// ---------------------------------------------------------------------------
#define SROWS 32

__device__ __forceinline__ void load_tile_bf16(float (*tile)[Wd],
                                               const __nv_bfloat16* __restrict__ ip,
                                               int r0, int tid)
{
    #pragma unroll
    for (int i = tid; i < 34 * 32; i += 256) {
        int rr = i >> 5, cg = (i & 31) << 2;
        int gr = r0 + rr;
        float4 v = make_float4(0.f, 0.f, 0.f, 0.f);
        if (gr >= 0 && gr < Hh) {
            uint2 u = *(const uint2*)&ip[gr * Wd + cg];
            __nv_bfloat162 lo = *(__nv_bfloat162*)&u.x;
            __nv_bfloat162 hi = *(__nv_bfloat162*)&u.y;
            v.x = __bfloat162float(lo.x); v.y = __bfloat162float(lo.y);
            v.z = __bfloat162float(hi.x); v.w = __bfloat162float(hi.y);
        }
        *(float4*)&tile[rr][cg] = v;
    }
}

__device__ __forceinline__ void ldrow(const float (*tile)[Wd], int r, int tx,
                                      float& m, float& c, float& p)
{
    c = tile[r][tx];
    m = (tx > 0)      ? tile[r][tx - 1] : 0.f;
    p = (tx < Wd - 1) ? tile[r][tx + 1] : 0.f;
}

// ---------------------------------------------------------------------------
// qkv depthwise conv: q,k -> fp32 g_t2 (+sumsq), v -> bf16 g_vb
// ---------------------------------------------------------------------------
__global__ void __launch_bounds__(256)
dwconv_qkv_kernel(const __nv_bfloat16* __restrict__ in, const float* __restrict__ w,
                  float* __restrict__ outqk, __nv_bfloat16* __restrict__ outv)
{
    __shared__ float tile[34][Wd];
    __shared__ float red[256];

    int strip = blockIdx.x & 3;
    int bc    = blockIdx.x >> 2;
    int c = bc % C3;
    int b = bc / C3;
    int tid = threadIdx.x;

    load_tile_bf16(tile, in + ((size_t)bc << 14), strip * SROWS - 1, tid);

    float wreg[9];
    #pragma unroll
    for (int i = 0; i < 9; i++) wreg[i] = __ldg(&w[(size_t)c * 9 + i]);
    __syncthreads();

    int tx   = tid & 127;
    int tseg = tid >> 7;
    int rb   = tseg * 16;

    float t0m, t0c, t0p, t1m, t1c, t1p, t2m, t2c, t2p;
    ldrow(tile, rb,     tx, t0m, t0c, t0p);
    ldrow(tile, rb + 1, tx, t1m, t1c, t1p);

    int po = (strip * SROWS + rb) * Wd + tx;

    if (c < 2 * C) {
        float* op = outqk + (((size_t)b * 2 * C + c) << 14) + po;
        float sq = 0.f;
        #pragma unroll
        for (int rr = 0; rr < 16; rr++) {
            ldrow(tile, rb + rr + 2, tx, t2m, t2c, t2p);
            float s = wreg[0] * t0m + wreg[1] * t0c + wreg[2] * t0p
                    + wreg[3] * t1m + wreg[4] * t1c + wreg[5] * t1p
                    + wreg[6] * t2m + wreg[7] * t2c + wreg[8] * t2p;
            op[rr * Wd] = s;
            sq += s * s;
            t0m = t1m; t0c = t1c; t0p = t1p;
            t1m = t2m; t1c = t2c; t1p = t2p;
        }
        red[tid] = sq;
        __syncthreads();
        #pragma unroll
        for (int st = 128; st > 0; st >>= 1) {
            if (tid < st) red[tid] += red[tid + st];
            __syncthreads();
        }
        if (tid == 0) atomicAdd(&g_sq[b * 2 * C + c], red[0]);
    } else {
        __nv_bfloat16* op = outv + (((size_t)b * C + (c - 2 * C)) << 14) + po;
        #pragma unroll
        for (int rr = 0; rr < 16; rr++) {
            ldrow(tile, rb + rr + 2, tx, t2m, t2c, t2p);
            float s = wreg[0] * t0m + wreg[1] * t0c + wreg[2] * t0p
                    + wreg[3] * t1m + wreg[4] * t1c + wreg[5] * t1p
                    + wreg[6] * t2m + wreg[7] * t2c + wreg[8] * t2p;
            op[rr * Wd] = __float2bfloat16(s);
            t0m = t1m; t0c = t1c; t0p = t1p;
            t1m = t2m; t1c = t2c; t1p = t2p;
        }
    }
}

// ---------------------------------------------------------------------------
// FFN depthwise conv + fused gelu gate (bf16 in/out)
// ---------------------------------------------------------------------------
__global__ void __launch_bounds__(256)
dwgate_kernel(const __nv_bfloat16* __restrict__ in, const float* __restrict__ w,
              __nv_bfloat16* __restrict__ out)
{
    __shared__ float tileA[34][Wd];
    __shared__ float tileB[34][Wd];

    int strip = blockIdx.x & 3;
    int bj    = blockIdx.x >> 2;
    int j = bj % HIDDEN;
    int b = bj / HIDDEN;
    int tid = threadIdx.x;

    int r0 = strip * SROWS - 1;
    load_tile_bf16(tileA, in + (((size_t)b * FF2 + j) << 14), r0, tid);
    load_tile_bf16(tileB, in + (((size_t)b * FF2 + HIDDEN + j) << 14), r0, tid);

    float wa[9], wb[9];
    #pragma unroll
    for (int i = 0; i < 9; i++) {
        wa[i] = __ldg(&w[(size_t)j * 9 + i]);
        wb[i] = __ldg(&w[(size_t)(HIDDEN + j) * 9 + i]);
    }
    __syncthreads();

    int tx   = tid & 127;
    int tseg = tid >> 7;
    int rb   = tseg * 16;

    float a0m, a0c, a0p, a1m, a1c, a1p, a2m, a2c, a2p;
    float b0m, b0c, b0p, b1m, b1c, b1p, b2m, b2c, b2p;
    ldrow(tileA, rb,     tx, a0m, a0c, a0p);
    ldrow(tileA, rb + 1, tx, a1m, a1c, a1p);
    ldrow(tileB, rb,     tx, b0m, b0c, b0p);
    ldrow(tileB, rb + 1, tx, b1m, b1c, b1p);

    __nv_bfloat16* op = out + (((size_t)b * HIDDEN + j) << 14) + (strip * SROWS + rb) * Wd + tx;

    #pragma unroll
    for (int rr = 0; rr < 16; rr++) {
        ldrow(tileA, rb + rr + 2, tx, a2m, a2c, a2p);
        ldrow(tileB, rb + rr + 2, tx, b2m, b2c, b2p);
        float s1 = wa[0] * a0m + wa[1] * a0c + wa[2] * a0p
                 + wa[3] * a1m + wa[4] * a1c + wa[5] * a1p
                 + wa[6] * a2m + wa[7] * a2c + wa[8] * a2p;
        float s2 = wb[0] * b0m + wb[1] * b0c + wb[2] * b0p
                 + wb[3] * b1m + wb[4] * b1c + wb[5] * b1p
                 + wb[6] * b2m + wb[7] * b2c + wb[8] * b2p;
        float gl = 0.5f * s1 * (1.f + erff(s1 * 0.70710678118654752f));
        op[rr * Wd] = __float2bfloat16(gl * s2);
        a0m = a1m; a0c = a1c; a0p = a1p;
        a1m = a2m; a1c = a2c; a1p = a2p;
        b0m = b1m; b0c = b1c; b0p = b1p;
        b1m = b2m; b1c = b2c; b1p = b2p;
    }
}

// ---------------------------------------------------------------------------
// zero accumulators / finalize norms
// ---------------------------------------------------------------------------
__global__ void zero_kernel()
{
    int i = blockIdx.x * 256 + threadIdx.x;
    if (i < Bq * HEADS * HD * HD) g_attn[i] = 0.f;
    if (i < Bq * 2 * C) g_sq[i] = 0.f;
}

__global__ void invfin_kernel()
{
    int i = blockIdx.x * 256 + threadIdx.x;
    if (i >= Bq * 2 * C) return;
    int b = i / (2 * C), c = i % (2 * C);
    float inv = 1.f / fmaxf(sqrtf(g_sq[i]), 1e-12f);
    if (c < C) g_invq[b * C + c] = inv;
    else       g_invk[b * C + c - C] = inv;
}

// ---------------------------------------------------------------------------
// Gram matrices (split-K atomics)
// ---------------------------------------------------------------------------
#define GSPLIT 16
#define GBK    128
__global__ void gram_kernel()
{
    int bh = blockIdx.x;
    int split = blockIdx.y;
    int b = bh >> 3, h = bh & 7;
    const float* qbase = g_t2 + ((size_t)b * 2 * C + h * HD) * HW;
    const float* kbase = g_t2 + ((size_t)b * 2 * C + C + h * HD) * HW;

    __shared__ float qs[HD][GBK + 4];
    __shared__ float ks[HD][GBK + 4];

    int tid = threadIdx.x;
    int tx = tid & 7, ty = tid >> 3;
    float acc[3][3] = {{0.f}};

    int p0 = split * (HW / GSPLIT);
    for (int t = 0; t < (HW / GSPLIT) / GBK; t++) {
        int pb = p0 + t * GBK;
        for (int i = tid; i < 2 * HD * GBK; i += 64) {
            int r = i >> 7, k = i & (GBK - 1);
            if (r < HD) qs[r][k]      = qbase[(size_t)r * HW + pb + k];
            else        ks[r - HD][k] = kbase[(size_t)(r - HD) * HW + pb + k];
        }
        __syncthreads();
        #pragma unroll 4
        for (int k = 0; k < GBK; k++) {
            float qv[3], kv[3];
            #pragma unroll
            for (int ii = 0; ii < 3; ii++) qv[ii] = qs[ty * 3 + ii][k];
            #pragma unroll
            for (int jj = 0; jj < 3; jj++) kv[jj] = ks[tx * 3 + jj][k];
            #pragma unroll
            for (int ii = 0; ii < 3; ii++)
                #pragma unroll
                for (int jj = 0; jj < 3; jj++) acc[ii][jj] += qv[ii] * kv[jj];
        }
        __syncthreads();
    }
    float* dst = g_attn + (size_t)bh * HD * HD;
    #pragma unroll
    for (int ii = 0; ii < 3; ii++)
        #pragma unroll
        for (int jj = 0; jj < 3; jj++)
            atomicAdd(&dst[(ty * 3 + ii) * HD + tx * 3 + jj], acc[ii][jj]);
}

// ---------------------------------------------------------------------------
// Softmax per row, fused l2norm scaling + temperature
// ---------------------------------------------------------------------------
__global__ void softmax_kernel(const float* __restrict__ temp)
{
    int bh = blockIdx.x;
    int b = bh >> 3, h = bh & 7;
    int i = threadIdx.x;
    if (i >= HD) return;
    float* row = g_attn + (size_t)bh * HD * HD + i * HD;
    float qi = g_invq[b * C + h * HD + i] * temp[h];
    float vals[HD];
    float mx = -1e30f;
    #pragma unroll
    for (int j = 0; j < HD; j++) {
        float v = row[j] * qi * g_invk[b * C + h * HD + j];
        vals[j] = v;
        mx = fmaxf(mx, v);
    }
    float s = 0.f;
    #pragma unroll
    for (int j = 0; j < HD; j++) { vals[j] = expf(vals[j] - mx); s += vals[j]; }
    float inv = 1.f / s;
    #pragma unroll
    for (int j = 0; j < HD; j++) row[j] = vals[j] * inv;
}

// ---------------------------------------------------------------------------
// wm = W_proj @ blockdiag(attn) -> bf16
// ---------------------------------------------------------------------------
__global__ void wm_kernel(const float* __restrict__ wproj)
{
    int idx = blockIdx.x * 256 + threadIdx.x;
    if (idx >= Bq * C * C) return;
    int cc = idx % C;
    int o  = (idx / C) % C;
    int b  = idx / (C * C);
    int h = cc / HD, ci = cc % HD;
    const float* wrow = wproj + (size_t)o * C + h * HD;
    const float* arow = g_attn + ((size_t)(b * HEADS + h) * HD) * HD + ci;
    float s = 0.f;
    #pragma unroll
    for (int d = 0; d < HD; d++) s += wrow[d] * arow[d * HD];
    g_wmb[idx] = __float2bfloat16(s);
}

// ---------------------------------------------------------------------------
// Launch sequence
// ---------------------------------------------------------------------------
extern "C" void kernel_launch(void* const* d_in, const int* in_sizes, int n_in,
                              void* d_out, int out_size)
{
    const float* x      = (const float*)d_in[0];
    const float* temp   = (const float*)d_in[1];
    const float* ln1w   = (const float*)d_in[2];
    const float* ln1b   = (const float*)d_in[3];
    const float* ln2w   = (const float*)d_in[4];
    const float* ln2b   = (const float*)d_in[5];
    const float* w_qkv  = (const float*)d_in[6];
    const float* w_qkvd = (const float*)d_in[7];
    const float* w_proj = (const float*)d_in[8];
    const float* w_in   = (const float*)d_in[9];
    const float* w_dw   = (const float*)d_in[10];
    const float* w_out  = (const float*)d_in[11];
    float* out = (float*)d_out;

    float *p_t2, *p_xmid;
    __nv_bfloat16 *p_t1b, *p_vb, *p_lnb, *p_gate, *p_wqkvb, *p_winb, *p_woutb, *p_wmb;
    cudaGetSymbolAddress((void**)&p_t2,    g_t2);
    cudaGetSymbolAddress((void**)&p_xmid,  g_xmid);
    cudaGetSymbolAddress((void**)&p_t1b,   g_t1b);
    cudaGetSymbolAddress((void**)&p_vb,    g_vb);
    cudaGetSymbolAddress((void**)&p_lnb,   g_lnb);
    cudaGetSymbolAddress((void**)&p_gate,  g_gate);
    cudaGetSymbolAddress((void**)&p_wqkvb, g_wqkvb);
    cudaGetSymbolAddress((void**)&p_winb,  g_winb);
    cudaGetSymbolAddress((void**)&p_woutb, g_woutb);
    cudaGetSymbolAddress((void**)&p_wmb,   g_wmb);

    const long sC   = (long)C * HW;
    const long sC3  = (long)C3 * HW;
    const long sFF2 = (long)FF2 * HW;
    const long sHID = (long)HIDDEN * HW;

    // 0. weight conversions
    convw_kernel<<<(C3 * C + 255) / 256, 256>>>(w_qkv, p_wqkvb, C3, C, C);
    convw_kernel<<<(FF2 * C + 255) / 256, 256>>>(w_in, p_winb, FF2, C, C);
    convw_kernel<<<(C * KOUTP + 255) / 256, 256>>>(w_out, p_woutb, C, HIDDEN, KOUTP);

    // 1. ln1(x) -> g_lnb
    ln_kernel<<<Bq * 256, 256>>>(x, ln1w, ln1b, p_lnb);

    // 2. qkv = W_qkv @ ln -> g_t1b (bf16)
    bf16_gemm_kernel<C, true><<<dim3(HW / BN, (C3 + BM - 1) / BM, Bq), 256>>>(
        p_wqkvb, p_lnb, p_t1b, nullptr, C3, C, 0, sC, sC3);

    // 3. zero accumulators
    zero_kernel<<<(Bq * HEADS * HD * HD + 255) / 256, 256>>>();

    // 4. tiled qkv depthwise 3x3: q,k->fp32+sumsq, v->bf16
    dwconv_qkv_kernel<<<Bq * C3 * 4, 256>>>(p_t1b, w_qkvd, p_t2, p_vb);

    // 5. finalize inverse norms
    invfin_kernel<<<(Bq * 2 * C + 255) / 256, 256>>>();

    // 6. q @ k^T gram matrices
    gram_kernel<<<dim3(Bq * HEADS, GSPLIT), 64>>>();

    // 7. softmax (fused normalization + temperature)
    softmax_kernel<<<Bq * HEADS, 32>>>(temp);

    // 8. wm = W_proj @ blockdiag(attn) -> bf16
    wm_kernel<<<(Bq * C * C + 255) / 256, 256>>>(w_proj);

    // 9. xmid = wm @ v + x   (v bf16, fp32 out + residual)
    bf16_gemm_kernel<C, false><<<dim3(HW / BN, (C + BM - 1) / BM, Bq), 256>>>(
        p_wmb, p_vb, p_xmid, x, C, C, (long)C * C, sC, sC);

    // 10. ln2(xmid) -> g_lnb
    ln_kernel<<<Bq * 256, 256>>>(p_xmid, ln2w, ln2b, p_lnb);

    // 11. ffn hidden = W_in @ ln -> g_t1b (bf16)
    bf16_gemm_kernel<C, true><<<dim3(HW / BN, (FF2 + BM - 1) / BM, Bq), 256>>>(
        p_winb, p_lnb, p_t1b, nullptr, FF2, C, 0, sC, sFF2);

    // 12. tiled depthwise 3x3 + gelu gate -> g_gate (bf16)
    dwgate_kernel<<<Bq * HIDDEN * 4, 256>>>(p_t1b, w_dw, p_gate);

    // 13. out = W_out @ gated + xmid  (K=512 padded, fp32 out + residual)
    bf16_gemm_kernel<KOUTP, false><<<dim3(HW / BN, (C + BM - 1) / BM, Bq), 256>>>(
        p_woutb, p_gate, out, p_xmid, C, HIDDEN, 0, sHID, sC);
}